// round 6
// baseline (speedup 1.0000x reference)
#include <cuda_runtime.h>
#include <math.h>
#include <stdint.h>

// Problem constants
#define DIMC   128
#define NWIN   49
#define HEADS  4
#define HD     32
#define NB     4096
#define M_TOTAL (NB * NWIN)        // 200704 = 1568 * 128

// Scratch (allocation-free rule: static device globals)
__device__ float g_qkv[(size_t)NB * NWIN * 384];   // [M, 384] : q|k|v per row
__device__ float g_att[(size_t)NB * NWIN * DIMC];  // [M, 128] : attention output
__device__ float g_comb[4 * 64 * 49 * 56];         // (bias+mask)/scale, [h][wm][i][j]

__device__ __forceinline__ float to_tf32(float x) {
    float r;
    asm("cvt.rna.tf32.f32 %0, %1;" : "=f"(r) : "f"(x));
    return r;
}
// round-to-nearest tf32 as raw bits (tensor core truncates low 13 bits)
__device__ __forceinline__ uint32_t rna_bits(float x) {
    return __float_as_uint(x) + 0x1000u;
}

__device__ __forceinline__ void mma_tf32(float c[4], const uint32_t a[4],
                                         uint32_t b0, uint32_t b1) {
    asm volatile(
        "mma.sync.aligned.m16n8k8.row.col.f32.tf32.tf32.f32 "
        "{%0,%1,%2,%3}, {%4,%5,%6,%7}, {%8,%9}, {%0,%1,%2,%3};"
        : "+f"(c[0]), "+f"(c[1]), "+f"(c[2]), "+f"(c[3])
        : "r"(a[0]), "r"(a[1]), "r"(a[2]), "r"(a[3]), "r"(b0), "r"(b1));
}

#define CP_ASYNC16(dst, src) \
    asm volatile("cp.async.ca.shared.global [%0], [%1], 16;" :: "r"(dst), "l"(src))
#define CP_COMMIT() asm volatile("cp.async.commit_group;")

// ---------------------------------------------------------------------------
// tf32 GEMM v4 (A-resident): C[M][NC] = A[M][128] * W[NC][128]^T + bias
// Block owns 128 rows and ALL NC columns (loop over NC/128 n-blocks), so A
// is read from DRAM exactly once. A resides in smem (stride 132: fragment
// LDS.32 conflict-free); W streams via a 3-chunk cp.async ring (stride 20).
// 8 warps (2m x 4n), warp tile 64x32 per n-block. tf32 RNA at fragment load.
// ---------------------------------------------------------------------------
#define A_RES_FLOATS (128 * 132)
#define W_RING_FLOATS (3 * 128 * 20)
#define GEMM4_SMEM ((A_RES_FLOATS + W_RING_FLOATS) * 4)

template<int NC>
__global__ __launch_bounds__(256, 2) void gemm_tc4_kernel(
    const float* __restrict__ A, const float* __restrict__ W,
    const float* __restrict__ bias, float* __restrict__ C)
{
    extern __shared__ float sm[];
    float* A_s = sm;                          // [128][132]
    float* W_s = sm + A_RES_FLOATS;           // [3][128][20]

    const int tid  = threadIdx.x;
    const int lane = tid & 31;
    const int warp = tid >> 5;
    const int wm   = warp & 1;
    const int wn   = warp >> 1;
    const int g    = lane >> 2;
    const int t    = lane & 3;
    const long m0  = (long)blockIdx.x * 128;
    const int NBLK = NC / 128;
    const int TOT  = 8 * NBLK;

    const uint32_t sbase = (uint32_t)__cvta_generic_to_shared(sm);
    const uint32_t wbase = sbase + A_RES_FLOATS * 4;

    // ---- stage resident A tile [128 x 128] (16 cp.async per thread) ----
    {
        const int row = tid >> 1, s0 = (tid & 1) * 16;
        const float* ga = A + (m0 + row) * 128 + s0 * 4;
        const uint32_t da = sbase + (row * 132 + s0 * 4) * 4;
        #pragma unroll
        for (int s2 = 0; s2 < 16; s2++)
            CP_ASYNC16(da + s2 * 16, ga + s2 * 4);
    }
    CP_COMMIT();

    // ---- W chunk stager: chunk kc2 covers n-block (kc2>>3), k cols (kc2&7)*16
    auto stageW = [&](int kc2) {
        const int buf = kc2 % 3, nb = kc2 >> 3, kc = kc2 & 7;
        const int r = tid >> 1;
        const float* gw = W + ((size_t)(nb * 128 + r)) * 128 + kc * 16 + (tid & 1) * 8;
        const uint32_t dw = wbase + (buf * 2560 + r * 20 + (tid & 1) * 8) * 4;
        CP_ASYNC16(dw,      gw);
        CP_ASYNC16(dw + 16, gw + 4);
    };
    stageW(0); CP_COMMIT();
    stageW(1); CP_COMMIT();

    float acc[4][4][4] = {};

    for (int nb = 0; nb < NBLK; nb++) {
        #pragma unroll
        for (int kc = 0; kc < 8; kc++) {
            const int kc2 = nb * 8 + kc;
            if (kc2 < TOT - 1) asm volatile("cp.async.wait_group 1;");
            else               asm volatile("cp.async.wait_group 0;");
            __syncthreads();
            if (kc2 + 2 < TOT) { stageW(kc2 + 2); CP_COMMIT(); }

            const float* Wb = W_s + (kc2 % 3) * 2560;
            #pragma unroll
            for (int s = 0; s < 2; s++) {
                const int off = kc * 16 + s * 8;
                uint32_t a[4][4];
                #pragma unroll
                for (int mt = 0; mt < 4; mt++) {
                    const int r = wm * 64 + mt * 16 + g;
                    a[mt][0] = rna_bits(A_s[r * 132 + off + t]);
                    a[mt][1] = rna_bits(A_s[(r + 8) * 132 + off + t]);
                    a[mt][2] = rna_bits(A_s[r * 132 + off + t + 4]);
                    a[mt][3] = rna_bits(A_s[(r + 8) * 132 + off + t + 4]);
                }
                #pragma unroll
                for (int nt = 0; nt < 4; nt++) {
                    const int n = wn * 32 + nt * 8 + g;
                    uint32_t b0 = rna_bits(Wb[n * 20 + s * 8 + t]);
                    uint32_t b1 = rna_bits(Wb[n * 20 + s * 8 + t + 4]);
                    #pragma unroll
                    for (int mt = 0; mt < 4; mt++)
                        mma_tf32(acc[mt][nt], a[mt], b0, b1);
                }
            }
        }

        // ---- epilogue for this n-block, then reset accumulators ----
        #pragma unroll
        for (int nt = 0; nt < 4; nt++) {
            const int col = nb * 128 + wn * 32 + nt * 8 + 2 * t;
            const float b0 = bias[col], b1 = bias[col + 1];
            #pragma unroll
            for (int mt = 0; mt < 4; mt++) {
                const long r = m0 + wm * 64 + mt * 16 + g;
                *(float2*)&C[r * NC + col] =
                    make_float2(acc[mt][nt][0] + b0, acc[mt][nt][1] + b1);
                *(float2*)&C[(r + 8) * NC + col] =
                    make_float2(acc[mt][nt][2] + b0, acc[mt][nt][3] + b1);
                acc[mt][nt][0] = 0.f; acc[mt][nt][1] = 0.f;
                acc[mt][nt][2] = 0.f; acc[mt][nt][3] = 0.f;
            }
        }
    }
}

// ---------------------------------------------------------------------------
// Precompute (rel-pos bias + shift mask) / scale : g_comb[h][wm][i][j(pad 56)]
// Pad cols j>=49 get -1e30 so softmax zeroes them.
// ---------------------------------------------------------------------------
__global__ void precomp_bias_mask(const float* __restrict__ mask,
                                  const float* __restrict__ bias_table,
                                  const int* __restrict__ rel_index)
{
    const int wm = blockIdx.x;   // 0..63
    const int h  = blockIdx.y;   // 0..3
    const float inv_scale = 5.656854249492381f;  // sqrt(32)
    float* dst = g_comb + ((size_t)h * 64 + wm) * 49 * 56;
    for (int q = threadIdx.x; q < 49 * 56; q += blockDim.x) {
        int i = q / 56, j = q - i * 56;
        dst[q] = (j < 49)
            ? (bias_table[rel_index[i * 49 + j] * HEADS + h]
               + mask[(size_t)wm * (NWIN * NWIN) + i * 49 + j]) * inv_scale
            : -1e30f;
    }
}

// ---------------------------------------------------------------------------
// Attention v4. Block = (window b, head h), 128 threads = 4 warps.
// cp.async staging of Q,K,V row-major (no transform). QK accumulators init
// from g_comb/scale (L2-hot); scale applied inside exp. Softmax in registers.
// P to smem natural layout; PV B-fragments read V row-major directly.
// tf32 RNA applied at fragment load. One __syncthreads + one __syncwarp.
// ---------------------------------------------------------------------------
__global__ __launch_bounds__(128) void attn_tc_kernel(
    const float* __restrict__ qkv, float* __restrict__ outp)
{
    __shared__ float Qs[64][40];   // rows 49..63 uninit (outputs masked)
    __shared__ float Ks[56][40];   // rows 49..55 zeroed
    __shared__ float Vs[56][40];   // rows 49..55 zeroed
    __shared__ float Ps[64][72];

    const int tid  = threadIdx.x;
    const int lane = tid & 31;
    const int warp = tid >> 5;
    const int g = lane >> 2, t = lane & 3;
    const int b = blockIdx.x >> 2, h = blockIdx.x & 3;
    const float scale = 0.17677669529663687f;   // 32^-0.5

    // ---- cp.async staging of Q, K, V (49 rows x 32 floats each) ----
    {
        const float* base = qkv + ((size_t)b * 49) * 384 + h * 32;
        const uint32_t sQ = (uint32_t)__cvta_generic_to_shared(&Qs[0][0]);
        const uint32_t sK = (uint32_t)__cvta_generic_to_shared(&Ks[0][0]);
        const uint32_t sV = (uint32_t)__cvta_generic_to_shared(&Vs[0][0]);
        for (int q = tid; q < 392; q += 128) {
            int i = q >> 3, seg = q & 7;
            CP_ASYNC16(sQ + (i * 40 + seg * 4) * 4, base + (size_t)i * 384 + seg * 4);
        }
        for (int q = tid; q < 392; q += 128) {
            int i = q >> 3, seg = q & 7;
            CP_ASYNC16(sK + (i * 40 + seg * 4) * 4, base + (size_t)i * 384 + 128 + seg * 4);
        }
        for (int q = tid; q < 392; q += 128) {
            int i = q >> 3, seg = q & 7;
            CP_ASYNC16(sV + (i * 40 + seg * 4) * 4, base + (size_t)i * 384 + 256 + seg * 4);
        }
        CP_COMMIT();
        // zero K/V pad rows (disjoint from cp.async targets)
        for (int q = tid; q < 7 * 40; q += 128) {
            int i = 49 + q / 40, c2 = q % 40;
            Ks[i][c2] = 0.f;
            Vs[i][c2] = 0.f;
        }
    }

    // ---- init S accumulators from comb/scale (overlaps with cp.async) ----
    const int r0 = warp * 16 + g;
    const float* comb = g_comb + ((size_t)h * 64 + (b & 63)) * 49 * 56;
    float c[7][4];
    #pragma unroll
    for (int nt = 0; nt < 7; nt++) {
        const int col = nt * 8 + 2 * t;
        if (r0 < 49) {
            float2 f = *(const float2*)&comb[r0 * 56 + col];
            c[nt][0] = f.x; c[nt][1] = f.y;
        } else { c[nt][0] = 0.f; c[nt][1] = 0.f; }
        if (r0 + 8 < 49) {
            float2 f = *(const float2*)&comb[(r0 + 8) * 56 + col];
            c[nt][2] = f.x; c[nt][3] = f.y;
        } else { c[nt][2] = 0.f; c[nt][3] = 0.f; }
    }

    asm volatile("cp.async.wait_group 0;");
    __syncthreads();

    // ---- S' = QK^T + comb/scale ----
    #pragma unroll
    for (int s = 0; s < 4; s++) {
        const int off = s * 8;
        uint32_t a[4];
        a[0] = rna_bits(Qs[r0][off + t]);
        a[1] = rna_bits(Qs[r0 + 8][off + t]);
        a[2] = rna_bits(Qs[r0][off + t + 4]);
        a[3] = rna_bits(Qs[r0 + 8][off + t + 4]);
        #pragma unroll
        for (int nt = 0; nt < 7; nt++) {
            uint32_t b0 = rna_bits(Ks[nt * 8 + g][off + t]);
            uint32_t b1 = rna_bits(Ks[nt * 8 + g][off + t + 4]);
            mma_tf32(c[nt], a, b0, b1);
        }
    }

    // ---- softmax(scale * S') in registers ----
    {
        float mx0 = -1e30f, mx1 = -1e30f;
        #pragma unroll
        for (int nt = 0; nt < 7; nt++) {
            mx0 = fmaxf(mx0, fmaxf(c[nt][0], c[nt][1]));
            mx1 = fmaxf(mx1, fmaxf(c[nt][2], c[nt][3]));
        }
        mx0 = fmaxf(mx0, __shfl_xor_sync(0xffffffffu, mx0, 1));
        mx0 = fmaxf(mx0, __shfl_xor_sync(0xffffffffu, mx0, 2));
        mx1 = fmaxf(mx1, __shfl_xor_sync(0xffffffffu, mx1, 1));
        mx1 = fmaxf(mx1, __shfl_xor_sync(0xffffffffu, mx1, 2));
        float s0 = 0.f, s1 = 0.f;
        #pragma unroll
        for (int nt = 0; nt < 7; nt++) {
            c[nt][0] = __expf((c[nt][0] - mx0) * scale);
            c[nt][1] = __expf((c[nt][1] - mx0) * scale);
            c[nt][2] = __expf((c[nt][2] - mx1) * scale);
            c[nt][3] = __expf((c[nt][3] - mx1) * scale);
            s0 += c[nt][0] + c[nt][1];
            s1 += c[nt][2] + c[nt][3];
        }
        s0 += __shfl_xor_sync(0xffffffffu, s0, 1);
        s0 += __shfl_xor_sync(0xffffffffu, s0, 2);
        s1 += __shfl_xor_sync(0xffffffffu, s1, 1);
        s1 += __shfl_xor_sync(0xffffffffu, s1, 2);
        const float i0 = 1.f / s0, i1 = 1.f / s1;

        #pragma unroll
        for (int nt = 0; nt < 7; nt++) {
            const int col = nt * 8 + 2 * t;
            *(float2*)&Ps[r0][col] =
                make_float2(to_tf32(c[nt][0] * i0), to_tf32(c[nt][1] * i0));
            *(float2*)&Ps[r0 + 8][col] =
                make_float2(to_tf32(c[nt][2] * i1), to_tf32(c[nt][3] * i1));
        }
    }
    __syncwarp();

    // ---- O = P V ----
    float o[4][4];
    #pragma unroll
    for (int nt = 0; nt < 4; nt++)
        #pragma unroll
        for (int e = 0; e < 4; e++) o[nt][e] = 0.f;

    #pragma unroll
    for (int s = 0; s < 7; s++) {
        const int off = s * 8;
        uint32_t a[4];
        a[0] = __float_as_uint(Ps[r0][off + t]);
        a[1] = __float_as_uint(Ps[r0 + 8][off + t]);
        a[2] = __float_as_uint(Ps[r0][off + t + 4]);
        a[3] = __float_as_uint(Ps[r0 + 8][off + t + 4]);
        #pragma unroll
        for (int nt = 0; nt < 4; nt++) {
            uint32_t b0 = rna_bits(Vs[off + t][nt * 8 + g]);
            uint32_t b1 = rna_bits(Vs[off + t + 4][nt * 8 + g]);
            mma_tf32(o[nt], a, b0, b1);
        }
    }

    #pragma unroll
    for (int nt = 0; nt < 4; nt++) {
        const int d = nt * 8 + 2 * t;
        if (r0 < 49)
            *(float2*)&outp[((size_t)b * 49 + r0) * DIMC + h * HD + d]
                = make_float2(o[nt][0], o[nt][1]);
        if (r0 + 8 < 49)
            *(float2*)&outp[((size_t)b * 49 + r0 + 8) * DIMC + h * HD + d]
                = make_float2(o[nt][2], o[nt][3]);
    }
}

// ---------------------------------------------------------------------------
extern "C" void kernel_launch(void* const* d_in, const int* in_sizes, int n_in,
                              void* d_out, int out_size)
{
    const float* x          = (const float*)d_in[0];
    const float* mask       = (const float*)d_in[1];
    const float* qkv_w      = (const float*)d_in[2];
    const float* qkv_b      = (const float*)d_in[3];
    const float* proj_w     = (const float*)d_in[4];
    const float* proj_b     = (const float*)d_in[5];
    const float* bias_table = (const float*)d_in[6];
    const int*   rel_index  = (const int*)d_in[7];
    float*       out        = (float*)d_out;

    float *qkvbuf = nullptr, *attbuf = nullptr;
    cudaGetSymbolAddress((void**)&qkvbuf, g_qkv);
    cudaGetSymbolAddress((void**)&attbuf, g_att);

    cudaFuncSetAttribute(gemm_tc4_kernel<384>,
                         cudaFuncAttributeMaxDynamicSharedMemorySize, GEMM4_SMEM);
    cudaFuncSetAttribute(gemm_tc4_kernel<DIMC>,
                         cudaFuncAttributeMaxDynamicSharedMemorySize, GEMM4_SMEM);

    dim3 gp(64, 4);
    precomp_bias_mask<<<gp, 256>>>(mask, bias_table, rel_index);

    gemm_tc4_kernel<384><<<M_TOTAL / 128, 256, GEMM4_SMEM>>>(x, qkv_w, qkv_b, qkvbuf);

    attn_tc_kernel<<<NB * HEADS, 128>>>(qkvbuf, attbuf);

    gemm_tc4_kernel<DIMC><<<M_TOTAL / 128, 256, GEMM4_SMEM>>>(attbuf, proj_w, proj_b, out);
}